// round 7
// baseline (speedup 1.0000x reference)
#include <cuda_runtime.h>
#include <cuda_bf16.h>
#include <cuda_fp16.h>
#include <cstdint>

#define BH    32
#define SEQ   2048
#define D     64
#define BQ    64
#define BK    64
#define NTILE (SEQ / BK)      // 32
#define NT    128             // 4 warps
#define PACKNT 256

#define QSCALE 0.18033688011112042f   // 0.125 * log2(e)

// packed tile image sizes (bytes)
#define KTILE_B 16384         // 64 kv rows x 256B (128 bf16 concat)
#define VTILE_B 8192          // 64 d rows x 128B (64 fp16 kv)

__device__ __align__(128) unsigned char gKH[BH * NTILE * KTILE_B];
__device__ __align__(128) unsigned char gKL[BH * NTILE * KTILE_B];
__device__ __align__(128) unsigned char gV [BH * NTILE * VTILE_B];

// smem: two stages of [KH | KL | V] + 2 mbarriers
#define STAGE_B  (KTILE_B + KTILE_B + VTILE_B)     // 40960
#define ST_KH 0
#define ST_KL 16384
#define ST_V  32768
#define SM_MBAR  (2 * STAGE_B)                     // 81920
#define SMEM_BYTES (SM_MBAR + 16)

__device__ __forceinline__ void split2(float x, float y, unsigned &hi, unsigned &lo) {
    __nv_bfloat162 h = __floats2bfloat162_rn(x, y);
    hi = *reinterpret_cast<unsigned*>(&h);
    float rx = x - __bfloat162float(h.x);
    float ry = y - __bfloat162float(h.y);
    __nv_bfloat162 l2 = __floats2bfloat162_rn(rx, ry);
    lo = *reinterpret_cast<unsigned*>(&l2);
}

// bf16 mma (QK^T split path)
#define MMAB(c, a, b0, b1)                                                     \
    asm volatile(                                                              \
        "mma.sync.aligned.m16n8k16.row.col.f32.bf16.bf16.f32 "                 \
        "{%0,%1,%2,%3},{%4,%5,%6,%7},{%8,%9},{%0,%1,%2,%3};"                   \
        : "+f"(c[0]), "+f"(c[1]), "+f"(c[2]), "+f"(c[3])                       \
        : "r"(a[0]), "r"(a[1]), "r"(a[2]), "r"(a[3]), "r"(b0), "r"(b1))

// fp16 mma (PV single-pass path)
#define MMAH(c, a, b0, b1)                                                     \
    asm volatile(                                                              \
        "mma.sync.aligned.m16n8k16.row.col.f32.f16.f16.f32 "                   \
        "{%0,%1,%2,%3},{%4,%5,%6,%7},{%8,%9},{%0,%1,%2,%3};"                   \
        : "+f"(c[0]), "+f"(c[1]), "+f"(c[2]), "+f"(c[3])                       \
        : "r"(a[0]), "r"(a[1]), "r"(a[2]), "r"(a[3]), "r"(b0), "r"(b1))

// ======================= pre-pass: pack K|Kp and V^T =======================
__global__ __launch_bounds__(PACKNT)
void pack_kv(const float* __restrict__ K, const float* __restrict__ Kp,
             const float* __restrict__ V)
{
    __shared__ float vs[BK][D + 4];

    const int kt = blockIdx.x, bh = blockIdx.y, tid = threadIdx.x;
    const long plane = (long)bh * SEQ * D;
    const float* Kt  = K  + plane + (long)kt * BK * D;
    const float* Kpt = Kp + plane + (long)kt * BK * D;
    const float* Vt  = V  + plane + (long)kt * BK * D;
    const size_t ti = (size_t)(bh * NTILE + kt);
    unsigned char* tKH = gKH + ti * KTILE_B;
    unsigned char* tKL = gKL + ti * KTILE_B;
    unsigned char* tV  = gV  + ti * VTILE_B;

    // K|Kp: rows=kv (256B), 64 b32-pair cols, 16B-chunk swizzle
    for (int i = tid; i < BK * 64; i += PACKNT) {
        int row = i >> 6, col = i & 63;
        const float* src = (col < 32) ? Kt : Kpt;
        float2 v = *(const float2*)&src[row * D + (col & 31) * 2];
        unsigned hi, lo; split2(v.x, v.y, hi, lo);
        unsigned off = row * 256 + (((col >> 2) ^ (row & 7)) << 4) + ((col & 3) << 2);
        *(unsigned*)(tKH + off) = hi;
        *(unsigned*)(tKL + off) = lo;
    }

    // V: coalesced gmem read -> smem, then coalesced transposed fp16 write
    for (int i = tid; i < BK * D; i += PACKNT) {
        int r = i >> 6, d = i & 63;
        vs[r][d] = Vt[r * D + d];
    }
    __syncthreads();
    for (int i = tid; i < D * 32; i += PACKNT) {
        int d = i >> 5, cp = i & 31;                 // d-row, kv pair
        __half2 h = __floats2half2_rn(vs[2 * cp][d], vs[2 * cp + 1][d]);
        unsigned off = d * 128 + (((cp >> 2) ^ (d & 7)) << 4) + ((cp & 3) << 2);
        *(unsigned*)(tV + off) = *reinterpret_cast<unsigned*>(&h);
    }
}

// =============================== main kernel ===============================
__device__ __forceinline__ uint32_t s2u32(const void* p) {
    uint32_t a;
    asm("{ .reg .u64 t; cvta.to.shared.u64 t, %1; cvt.u32.u64 %0, t; }" : "=r"(a) : "l"(p));
    return a;
}

__device__ __forceinline__ void bulk_g2s(uint32_t dst, const void* src,
                                         unsigned bytes, uint32_t mbar) {
    asm volatile(
        "cp.async.bulk.shared::cluster.global.mbarrier::complete_tx::bytes "
        "[%0], [%1], %2, [%3];"
        :: "r"(dst), "l"(src), "r"(bytes), "r"(mbar) : "memory");
}

__global__ __launch_bounds__(NT, 2)
void fa4_mma_kernel(const float* __restrict__ Qg,
                    const float* __restrict__ Qpg,
                    float* __restrict__ Og)
{
    extern __shared__ unsigned char sm[];
    const uint32_t smb = s2u32(sm);

    const int bh    = blockIdx.y;
    const int qtile = blockIdx.x;
    const int tid   = threadIdx.x;
    const int w     = tid >> 5;
    const int lane  = tid & 31;
    const int g     = lane >> 2;
    const int t     = lane & 3;

    const long plane = (long)bh * SEQ * D;

    if (tid == 0) {
        asm volatile("mbarrier.init.shared.b64 [%0], 1;" :: "r"(smb + SM_MBAR) : "memory");
        asm volatile("mbarrier.init.shared.b64 [%0], 1;" :: "r"(smb + SM_MBAR + 8) : "memory");
    }
    __syncthreads();

    // ---- Q fragments in registers (scale = 0.125*log2e folded in) ----
    unsigned qhi[8][4], qlo[8][4];
    {
        const float* Qpl  = Qg  + plane;
        const float* Qppl = Qpg + plane;
        const int r0 = qtile * BQ + w * 16 + g;
        #pragma unroll
        for (int c = 0; c < 8; c++) {
            const float* S = (c < 4) ? Qpl : Qppl;
            const int cb = (c & 3) * 16;
            float2 x0 = *(const float2*)&S[(long)r0 * D + cb + 2 * t];
            float2 x1 = *(const float2*)&S[(long)(r0 + 8) * D + cb + 2 * t];
            float2 x2 = *(const float2*)&S[(long)r0 * D + cb + 8 + 2 * t];
            float2 x3 = *(const float2*)&S[(long)(r0 + 8) * D + cb + 8 + 2 * t];
            split2(x0.x * QSCALE, x0.y * QSCALE, qhi[c][0], qlo[c][0]);
            split2(x1.x * QSCALE, x1.y * QSCALE, qhi[c][1], qlo[c][1]);
            split2(x2.x * QSCALE, x2.y * QSCALE, qhi[c][2], qlo[c][2]);
            split2(x3.x * QSCALE, x3.y * QSCALE, qhi[c][3], qlo[c][3]);
        }
    }

    float ov[8][4];
    #pragma unroll
    for (int j = 0; j < 8; j++) { ov[j][0]=0.f; ov[j][1]=0.f; ov[j][2]=0.f; ov[j][3]=0.f; }
    float m0 = -1e30f, m1 = -1e30f, l0 = 0.f, l1 = 0.f;

    auto issue = [&](int kt, int s) {
        if (tid == 0) {
            const uint32_t mb = smb + SM_MBAR + s * 8;
            asm volatile("mbarrier.arrive.expect_tx.shared.b64 _, [%0], %1;"
                         :: "r"(mb), "r"((unsigned)STAGE_B) : "memory");
            const size_t ti = (size_t)(bh * NTILE + kt);
            const uint32_t sb = smb + s * STAGE_B;
            bulk_g2s(sb + ST_KH, gKH + ti * KTILE_B, KTILE_B, mb);
            bulk_g2s(sb + ST_KL, gKL + ti * KTILE_B, KTILE_B, mb);
            bulk_g2s(sb + ST_V,  gV  + ti * VTILE_B, VTILE_B, mb);
        }
    };

    issue(0, 0);

    for (int kt = 0; kt < NTILE; kt++) {
        const int s = kt & 1;
        if (kt + 1 < NTILE) issue(kt + 1, s ^ 1);

        {   // wait full(stage s)
            const uint32_t mb = smb + SM_MBAR + s * 8;
            const unsigned ph = (kt >> 1) & 1;
            unsigned done = 0;
            while (!done) {
                asm volatile(
                    "{ .reg .pred p; "
                    "mbarrier.try_wait.parity.acquire.cta.shared::cta.b64 p, [%1], %2; "
                    "selp.b32 %0, 1, 0, p; }"
                    : "=r"(done) : "r"(mb), "r"(ph) : "memory");
            }
        }

        unsigned char* KH = sm + s * STAGE_B + ST_KH;
        unsigned char* KL = sm + s * STAGE_B + ST_KL;
        unsigned char* VS = sm + s * STAGE_B + ST_V;

        // ---- QK^T: 3-MMA split bf16 ----
        float sc[8][4];
        #pragma unroll
        for (int j = 0; j < 8; j++) { sc[j][0]=0.f; sc[j][1]=0.f; sc[j][2]=0.f; sc[j][3]=0.f; }

        #pragma unroll
        for (int c = 0; c < 8; c++) {
            #pragma unroll
            for (int jp = 0; jp < 4; jp++) {
                const int j0 = 2 * jp, j1 = 2 * jp + 1;
                const unsigned base0 = (8 * j0 + g) * 256 + (t << 2);
                const unsigned base1 = (8 * j1 + g) * 256 + (t << 2);
                const unsigned ch0 = ((2 * c) ^ g) << 4, ch1 = ((2 * c + 1) ^ g) << 4;
                unsigned ah0 = *(const unsigned*)(KH + base0 + ch0);
                unsigned ah1 = *(const unsigned*)(KH + base0 + ch1);
                unsigned bh0 = *(const unsigned*)(KH + base1 + ch0);
                unsigned bh1 = *(const unsigned*)(KH + base1 + ch1);
                unsigned al0 = *(const unsigned*)(KL + base0 + ch0);
                unsigned al1 = *(const unsigned*)(KL + base0 + ch1);
                unsigned bl0 = *(const unsigned*)(KL + base1 + ch0);
                unsigned bl1 = *(const unsigned*)(KL + base1 + ch1);
                MMAB(sc[j0], qhi[c], ah0, ah1);
                MMAB(sc[j1], qhi[c], bh0, bh1);
                MMAB(sc[j0], qhi[c], al0, al1);
                MMAB(sc[j1], qhi[c], bl0, bl1);
                MMAB(sc[j0], qlo[c], ah0, ah1);
                MMAB(sc[j1], qlo[c], bh0, bh1);
            }
        }

        // ---- online softmax (log2 domain) ----
        float mx0 = -1e30f, mx1 = -1e30f;
        #pragma unroll
        for (int j = 0; j < 8; j++) {
            mx0 = fmaxf(mx0, fmaxf(sc[j][0], sc[j][1]));
            mx1 = fmaxf(mx1, fmaxf(sc[j][2], sc[j][3]));
        }
        mx0 = fmaxf(mx0, __shfl_xor_sync(0xffffffffu, mx0, 1));
        mx0 = fmaxf(mx0, __shfl_xor_sync(0xffffffffu, mx0, 2));
        mx1 = fmaxf(mx1, __shfl_xor_sync(0xffffffffu, mx1, 1));
        mx1 = fmaxf(mx1, __shfl_xor_sync(0xffffffffu, mx1, 2));

        float mn0 = fmaxf(m0, mx0), mn1 = fmaxf(m1, mx1);
        float f0 = exp2f(m0 - mn0), f1 = exp2f(m1 - mn1);
        m0 = mn0; m1 = mn1;

        float s0 = 0.f, s1 = 0.f;
        #pragma unroll
        for (int j = 0; j < 8; j++) {
            sc[j][0] = exp2f(sc[j][0] - m0); s0 += sc[j][0];
            sc[j][1] = exp2f(sc[j][1] - m0); s0 += sc[j][1];
            sc[j][2] = exp2f(sc[j][2] - m1); s1 += sc[j][2];
            sc[j][3] = exp2f(sc[j][3] - m1); s1 += sc[j][3];
        }
        s0 += __shfl_xor_sync(0xffffffffu, s0, 1);
        s0 += __shfl_xor_sync(0xffffffffu, s0, 2);
        s1 += __shfl_xor_sync(0xffffffffu, s1, 1);
        s1 += __shfl_xor_sync(0xffffffffu, s1, 2);
        l0 = l0 * f0 + s0;
        l1 = l1 * f1 + s1;

        #pragma unroll
        for (int j = 0; j < 8; j++) {
            ov[j][0] *= f0; ov[j][1] *= f0; ov[j][2] *= f1; ov[j][3] *= f1;
        }

        // ---- PV: single fp16 MMA (P,V in fp16; fp32 accum) ----
        #pragma unroll
        for (int c2 = 0; c2 < 4; c2++) {
            unsigned pa[4];
            __half2 h0 = __floats2half2_rn(sc[2*c2][0],   sc[2*c2][1]);
            __half2 h1 = __floats2half2_rn(sc[2*c2][2],   sc[2*c2][3]);
            __half2 h2 = __floats2half2_rn(sc[2*c2+1][0], sc[2*c2+1][1]);
            __half2 h3 = __floats2half2_rn(sc[2*c2+1][2], sc[2*c2+1][3]);
            pa[0] = *reinterpret_cast<unsigned*>(&h0);
            pa[1] = *reinterpret_cast<unsigned*>(&h1);
            pa[2] = *reinterpret_cast<unsigned*>(&h2);
            pa[3] = *reinterpret_cast<unsigned*>(&h3);
            #pragma unroll
            for (int jp = 0; jp < 4; jp++) {
                const int j0 = 2 * jp, j1 = 2 * jp + 1;
                const unsigned base0 = (8 * j0 + g) * 128 + (t << 2);
                const unsigned base1 = (8 * j1 + g) * 128 + (t << 2);
                const unsigned ch0 = ((2 * c2) ^ g) << 4, ch1 = ((2 * c2 + 1) ^ g) << 4;
                unsigned v00 = *(const unsigned*)(VS + base0 + ch0);
                unsigned v01 = *(const unsigned*)(VS + base0 + ch1);
                unsigned v10 = *(const unsigned*)(VS + base1 + ch0);
                unsigned v11 = *(const unsigned*)(VS + base1 + ch1);
                MMAH(ov[j0], pa, v00, v01);
                MMAH(ov[j1], pa, v10, v11);
            }
        }

        __syncthreads();   // stage s fully consumed before reuse
    }

    // ---- epilogue ----
    {
        float inv0 = 1.0f / l0, inv1 = 1.0f / l1;
        const int r0 = qtile * BQ + w * 16 + g;
        float* O = Og + plane;
        #pragma unroll
        for (int jd = 0; jd < 8; jd++) {
            int col = 8 * jd + 2 * t;
            float2 a = make_float2(ov[jd][0] * inv0, ov[jd][1] * inv0);
            float2 b = make_float2(ov[jd][2] * inv1, ov[jd][3] * inv1);
            *(float2*)&O[(long)r0 * D + col]       = a;
            *(float2*)&O[(long)(r0 + 8) * D + col] = b;
        }
    }
}

extern "C" void kernel_launch(void* const* d_in, const int* in_sizes, int n_in,
                              void* d_out, int out_size)
{
    const float* Q  = (const float*)d_in[0];
    const float* K  = (const float*)d_in[1];
    const float* V  = (const float*)d_in[2];
    const float* Qp = (const float*)d_in[3];
    const float* Kp = (const float*)d_in[4];
    float* O = (float*)d_out;

    cudaFuncSetAttribute(fa4_mma_kernel,
                         cudaFuncAttributeMaxDynamicSharedMemorySize, SMEM_BYTES);

    dim3 pgrid(NTILE, BH);
    pack_kv<<<pgrid, PACKNT>>>(K, Kp, V);

    dim3 grid(SEQ / BQ, BH);
    fa4_mma_kernel<<<grid, NT, SMEM_BYTES>>>(Q, Qp, O);
}

// round 8
// speedup vs baseline: 1.3573x; 1.3573x over previous
#include <cuda_runtime.h>
#include <cuda_bf16.h>
#include <cuda_fp16.h>
#include <cstdint>

#define BH    32
#define SEQ   2048
#define D     64
#define BQ    128
#define BK    64
#define NTILE (SEQ / BK)      // 32
#define NW    8
#define NT    256
#define PACKNT 256
#define NSTAGE 3

#define QSCALE 0.18033688011112042f   // 0.125 * log2(e)

// packed tile image sizes (bytes)
#define KTILE_B 16384         // 64 kv rows x 256B (128 bf16 concat)
#define VTILE_B 8192          // 64 d rows x 128B (64 fp16 kv)

__device__ __align__(128) unsigned char gKH[BH * NTILE * KTILE_B];
__device__ __align__(128) unsigned char gKL[BH * NTILE * KTILE_B];
__device__ __align__(128) unsigned char gV [BH * NTILE * VTILE_B];

// smem: NSTAGE stages of [KH | KL | V] + mbarriers (full[3], empty[3])
#define STAGE_B  (KTILE_B + KTILE_B + VTILE_B)     // 40960
#define ST_KH 0
#define ST_KL 16384
#define ST_V  32768
#define SM_MBAR  (NSTAGE * STAGE_B)                // 122880
#define SMEM_BYTES (SM_MBAR + 64)

__device__ __forceinline__ void split2(float x, float y, unsigned &hi, unsigned &lo) {
    __nv_bfloat162 h = __floats2bfloat162_rn(x, y);
    hi = *reinterpret_cast<unsigned*>(&h);
    float rx = x - __bfloat162float(h.x);
    float ry = y - __bfloat162float(h.y);
    __nv_bfloat162 l2 = __floats2bfloat162_rn(rx, ry);
    lo = *reinterpret_cast<unsigned*>(&l2);
}

#define MMAB(c, a, b0, b1)                                                     \
    asm volatile(                                                              \
        "mma.sync.aligned.m16n8k16.row.col.f32.bf16.bf16.f32 "                 \
        "{%0,%1,%2,%3},{%4,%5,%6,%7},{%8,%9},{%0,%1,%2,%3};"                   \
        : "+f"(c[0]), "+f"(c[1]), "+f"(c[2]), "+f"(c[3])                       \
        : "r"(a[0]), "r"(a[1]), "r"(a[2]), "r"(a[3]), "r"(b0), "r"(b1))

#define MMAH(c, a, b0, b1)                                                     \
    asm volatile(                                                              \
        "mma.sync.aligned.m16n8k16.row.col.f32.f16.f16.f32 "                   \
        "{%0,%1,%2,%3},{%4,%5,%6,%7},{%8,%9},{%0,%1,%2,%3};"                   \
        : "+f"(c[0]), "+f"(c[1]), "+f"(c[2]), "+f"(c[3])                       \
        : "r"(a[0]), "r"(a[1]), "r"(a[2]), "r"(a[3]), "r"(b0), "r"(b1))

// ======================= pre-pass: pack K|Kp and V^T =======================
__global__ __launch_bounds__(PACKNT)
void pack_kv(const float* __restrict__ K, const float* __restrict__ Kp,
             const float* __restrict__ V)
{
    __shared__ float vs[BK][D + 4];

    const int kt = blockIdx.x, bh = blockIdx.y, tid = threadIdx.x;
    const long plane = (long)bh * SEQ * D;
    const float* Kt  = K  + plane + (long)kt * BK * D;
    const float* Kpt = Kp + plane + (long)kt * BK * D;
    const float* Vt  = V  + plane + (long)kt * BK * D;
    const size_t ti = (size_t)(bh * NTILE + kt);
    unsigned char* tKH = gKH + ti * KTILE_B;
    unsigned char* tKL = gKL + ti * KTILE_B;
    unsigned char* tV  = gV  + ti * VTILE_B;

    // K|Kp: rows=kv (256B), 64 b32-pair cols, 16B-chunk swizzle
    for (int i = tid; i < BK * 64; i += PACKNT) {
        int row = i >> 6, col = i & 63;
        const float* src = (col < 32) ? Kt : Kpt;
        float2 v = *(const float2*)&src[row * D + (col & 31) * 2];
        unsigned hi, lo; split2(v.x, v.y, hi, lo);
        unsigned off = row * 256 + (((col >> 2) ^ (row & 7)) << 4) + ((col & 3) << 2);
        *(unsigned*)(tKH + off) = hi;
        *(unsigned*)(tKL + off) = lo;
    }

    // V: coalesced gmem read -> smem, then coalesced transposed fp16 write
    for (int i = tid; i < BK * D; i += PACKNT) {
        int r = i >> 6, d = i & 63;
        vs[r][d] = Vt[r * D + d];
    }
    __syncthreads();
    for (int i = tid; i < D * 32; i += PACKNT) {
        int d = i >> 5, cp = i & 31;                 // d-row, kv pair
        __half2 h = __floats2half2_rn(vs[2 * cp][d], vs[2 * cp + 1][d]);
        unsigned off = d * 128 + (((cp >> 2) ^ (d & 7)) << 4) + ((cp & 3) << 2);
        *(unsigned*)(tV + off) = *reinterpret_cast<unsigned*>(&h);
    }
}

// =============================== main kernel ===============================
__device__ __forceinline__ uint32_t s2u32(const void* p) {
    uint32_t a;
    asm("{ .reg .u64 t; cvta.to.shared.u64 t, %1; cvt.u32.u64 %0, t; }" : "=r"(a) : "l"(p));
    return a;
}

__device__ __forceinline__ void bulk_g2s(uint32_t dst, const void* src,
                                         unsigned bytes, uint32_t mbar) {
    asm volatile(
        "cp.async.bulk.shared::cluster.global.mbarrier::complete_tx::bytes "
        "[%0], [%1], %2, [%3];"
        :: "r"(dst), "l"(src), "r"(bytes), "r"(mbar) : "memory");
}

__device__ __forceinline__ void mbar_wait(uint32_t mbar, unsigned ph) {
    unsigned done = 0;
    while (!done) {
        asm volatile(
            "{ .reg .pred p; "
            "mbarrier.try_wait.parity.acquire.cta.shared::cta.b64 p, [%1], %2, 0x989680; "
            "selp.b32 %0, 1, 0, p; }"
            : "=r"(done) : "r"(mbar), "r"(ph) : "memory");
    }
}

__global__ __launch_bounds__(NT, 1)
void fa5_mma_kernel(const float* __restrict__ Qg,
                    const float* __restrict__ Qpg,
                    float* __restrict__ Og)
{
    extern __shared__ unsigned char sm[];
    const uint32_t smb = s2u32(sm);

    const int bh    = blockIdx.y;
    const int qtile = blockIdx.x;
    const int tid   = threadIdx.x;
    const int w     = tid >> 5;
    const int lane  = tid & 31;
    const int g     = lane >> 2;
    const int t     = lane & 3;

    const long plane = (long)bh * SEQ * D;

    // full[s] at SM_MBAR + s*8 (count 1, tx); empty[s] at SM_MBAR + 24 + s*8 (count NW)
    if (tid == 0) {
        #pragma unroll
        for (int s = 0; s < NSTAGE; s++) {
            asm volatile("mbarrier.init.shared.b64 [%0], 1;"
                         :: "r"(smb + SM_MBAR + s * 8) : "memory");
            asm volatile("mbarrier.init.shared.b64 [%0], %1;"
                         :: "r"(smb + SM_MBAR + 24 + s * 8), "r"(NW) : "memory");
        }
    }
    __syncthreads();

    // ---- Q fragments in registers (scale = 0.125*log2e folded in) ----
    unsigned qhi[8][4], qlo[8][4];
    {
        const float* Qpl  = Qg  + plane;
        const float* Qppl = Qpg + plane;
        const int r0 = qtile * BQ + w * 16 + g;
        #pragma unroll
        for (int c = 0; c < 8; c++) {
            const float* S = (c < 4) ? Qpl : Qppl;
            const int cb = (c & 3) * 16;
            float2 x0 = *(const float2*)&S[(long)r0 * D + cb + 2 * t];
            float2 x1 = *(const float2*)&S[(long)(r0 + 8) * D + cb + 2 * t];
            float2 x2 = *(const float2*)&S[(long)r0 * D + cb + 8 + 2 * t];
            float2 x3 = *(const float2*)&S[(long)(r0 + 8) * D + cb + 8 + 2 * t];
            split2(x0.x * QSCALE, x0.y * QSCALE, qhi[c][0], qlo[c][0]);
            split2(x1.x * QSCALE, x1.y * QSCALE, qhi[c][1], qlo[c][1]);
            split2(x2.x * QSCALE, x2.y * QSCALE, qhi[c][2], qlo[c][2]);
            split2(x3.x * QSCALE, x3.y * QSCALE, qhi[c][3], qlo[c][3]);
        }
    }

    float ov[8][4];
    #pragma unroll
    for (int j = 0; j < 8; j++) { ov[j][0]=0.f; ov[j][1]=0.f; ov[j][2]=0.f; ov[j][3]=0.f; }
    float m0 = -1e30f, m1 = -1e30f, l0 = 0.f, l1 = 0.f;

    auto issue = [&](int T) {            // producer: load tile T into stage T%3
        const int s = T % NSTAGE;
        const uint32_t mb = smb + SM_MBAR + s * 8;
        asm volatile("mbarrier.arrive.expect_tx.shared.b64 _, [%0], %1;"
                     :: "r"(mb), "r"((unsigned)STAGE_B) : "memory");
        const size_t ti = (size_t)(bh * NTILE + T);
        const uint32_t sb = smb + s * STAGE_B;
        bulk_g2s(sb + ST_KH, gKH + ti * KTILE_B, KTILE_B, mb);
        bulk_g2s(sb + ST_KL, gKL + ti * KTILE_B, KTILE_B, mb);
        bulk_g2s(sb + ST_V,  gV  + ti * VTILE_B, VTILE_B, mb);
    };

    if (tid == 0) { issue(0); issue(1); issue(2); }

    for (int kt = 0; kt < NTILE; kt++) {
        const int s = kt % NSTAGE;
        const unsigned rph = (unsigned)((kt / NSTAGE) & 1);

        // consumer: wait stage full
        mbar_wait(smb + SM_MBAR + s * 8, rph);

        unsigned char* KH = sm + s * STAGE_B + ST_KH;
        unsigned char* KL = sm + s * STAGE_B + ST_KL;
        unsigned char* VS = sm + s * STAGE_B + ST_V;

        // ---- QK^T: 3-MMA split bf16 ----
        float sc[8][4];
        #pragma unroll
        for (int j = 0; j < 8; j++) { sc[j][0]=0.f; sc[j][1]=0.f; sc[j][2]=0.f; sc[j][3]=0.f; }

        #pragma unroll
        for (int c = 0; c < 8; c++) {
            #pragma unroll
            for (int jp = 0; jp < 4; jp++) {
                const int j0 = 2 * jp, j1 = 2 * jp + 1;
                const unsigned base0 = (8 * j0 + g) * 256 + (t << 2);
                const unsigned base1 = (8 * j1 + g) * 256 + (t << 2);
                const unsigned ch0 = ((2 * c) ^ g) << 4, ch1 = ((2 * c + 1) ^ g) << 4;
                unsigned ah0 = *(const unsigned*)(KH + base0 + ch0);
                unsigned ah1 = *(const unsigned*)(KH + base0 + ch1);
                unsigned bh0 = *(const unsigned*)(KH + base1 + ch0);
                unsigned bh1 = *(const unsigned*)(KH + base1 + ch1);
                unsigned al0 = *(const unsigned*)(KL + base0 + ch0);
                unsigned al1 = *(const unsigned*)(KL + base0 + ch1);
                unsigned bl0 = *(const unsigned*)(KL + base1 + ch0);
                unsigned bl1 = *(const unsigned*)(KL + base1 + ch1);
                MMAB(sc[j0], qhi[c], ah0, ah1);
                MMAB(sc[j1], qhi[c], bh0, bh1);
                MMAB(sc[j0], qhi[c], al0, al1);
                MMAB(sc[j1], qhi[c], bl0, bl1);
                MMAB(sc[j0], qlo[c], ah0, ah1);
                MMAB(sc[j1], qlo[c], bh0, bh1);
            }
        }

        // ---- online softmax (log2 domain) ----
        float mx0 = -1e30f, mx1 = -1e30f;
        #pragma unroll
        for (int j = 0; j < 8; j++) {
            mx0 = fmaxf(mx0, fmaxf(sc[j][0], sc[j][1]));
            mx1 = fmaxf(mx1, fmaxf(sc[j][2], sc[j][3]));
        }
        mx0 = fmaxf(mx0, __shfl_xor_sync(0xffffffffu, mx0, 1));
        mx0 = fmaxf(mx0, __shfl_xor_sync(0xffffffffu, mx0, 2));
        mx1 = fmaxf(mx1, __shfl_xor_sync(0xffffffffu, mx1, 1));
        mx1 = fmaxf(mx1, __shfl_xor_sync(0xffffffffu, mx1, 2));

        float mn0 = fmaxf(m0, mx0), mn1 = fmaxf(m1, mx1);
        float f0 = exp2f(m0 - mn0), f1 = exp2f(m1 - mn1);
        m0 = mn0; m1 = mn1;

        float s0 = 0.f, s1 = 0.f;
        #pragma unroll
        for (int j = 0; j < 8; j++) {
            sc[j][0] = exp2f(sc[j][0] - m0); s0 += sc[j][0];
            sc[j][1] = exp2f(sc[j][1] - m0); s0 += sc[j][1];
            sc[j][2] = exp2f(sc[j][2] - m1); s1 += sc[j][2];
            sc[j][3] = exp2f(sc[j][3] - m1); s1 += sc[j][3];
        }
        s0 += __shfl_xor_sync(0xffffffffu, s0, 1);
        s0 += __shfl_xor_sync(0xffffffffu, s0, 2);
        s1 += __shfl_xor_sync(0xffffffffu, s1, 1);
        s1 += __shfl_xor_sync(0xffffffffu, s1, 2);
        l0 = l0 * f0 + s0;
        l1 = l1 * f1 + s1;

        #pragma unroll
        for (int j = 0; j < 8; j++) {
            ov[j][0] *= f0; ov[j][1] *= f0; ov[j][2] *= f1; ov[j][3] *= f1;
        }

        // ---- PV: single fp16 MMA (P,V fp16; fp32 accum) ----
        #pragma unroll
        for (int c2 = 0; c2 < 4; c2++) {
            unsigned pa[4];
            __half2 h0 = __floats2half2_rn(sc[2*c2][0],   sc[2*c2][1]);
            __half2 h1 = __floats2half2_rn(sc[2*c2][2],   sc[2*c2][3]);
            __half2 h2 = __floats2half2_rn(sc[2*c2+1][0], sc[2*c2+1][1]);
            __half2 h3 = __floats2half2_rn(sc[2*c2+1][2], sc[2*c2+1][3]);
            pa[0] = *reinterpret_cast<unsigned*>(&h0);
            pa[1] = *reinterpret_cast<unsigned*>(&h1);
            pa[2] = *reinterpret_cast<unsigned*>(&h2);
            pa[3] = *reinterpret_cast<unsigned*>(&h3);
            #pragma unroll
            for (int jp = 0; jp < 4; jp++) {
                const int j0 = 2 * jp, j1 = 2 * jp + 1;
                const unsigned base0 = (8 * j0 + g) * 128 + (t << 2);
                const unsigned base1 = (8 * j1 + g) * 128 + (t << 2);
                const unsigned ch0 = ((2 * c2) ^ g) << 4, ch1 = ((2 * c2 + 1) ^ g) << 4;
                unsigned v00 = *(const unsigned*)(VS + base0 + ch0);
                unsigned v01 = *(const unsigned*)(VS + base0 + ch1);
                unsigned v10 = *(const unsigned*)(VS + base1 + ch0);
                unsigned v11 = *(const unsigned*)(VS + base1 + ch1);
                MMAH(ov[j0], pa, v00, v01);
                MMAH(ov[j1], pa, v10, v11);
            }
        }

        // consumer: this warp is done with stage s
        if (lane == 0) {
            asm volatile("mbarrier.arrive.shared.b64 _, [%0];"
                         :: "r"(smb + SM_MBAR + 24 + s * 8) : "memory");
        }

        // producer: refill stage s with tile kt+3 once all 8 warps arrived
        if (tid == 0 && kt + NSTAGE < NTILE) {
            mbar_wait(smb + SM_MBAR + 24 + s * 8, rph);
            issue(kt + NSTAGE);
        }
    }

    // ---- epilogue ----
    {
        float inv0 = 1.0f / l0, inv1 = 1.0f / l1;
        const int r0 = qtile * BQ + w * 16 + g;
        float* O = Og + plane;
        #pragma unroll
        for (int jd = 0; jd < 8; jd++) {
            int col = 8 * jd + 2 * t;
            float2 a = make_float2(ov[jd][0] * inv0, ov[jd][1] * inv0);
            float2 b = make_float2(ov[jd][2] * inv1, ov[jd][3] * inv1);
            *(float2*)&O[(long)r0 * D + col]       = a;
            *(float2*)&O[(long)(r0 + 8) * D + col] = b;
        }
    }
}

extern "C" void kernel_launch(void* const* d_in, const int* in_sizes, int n_in,
                              void* d_out, int out_size)
{
    const float* Q  = (const float*)d_in[0];
    const float* K  = (const float*)d_in[1];
    const float* V  = (const float*)d_in[2];
    const float* Qp = (const float*)d_in[3];
    const float* Kp = (const float*)d_in[4];
    float* O = (float*)d_out;

    cudaFuncSetAttribute(fa5_mma_kernel,
                         cudaFuncAttributeMaxDynamicSharedMemorySize, SMEM_BYTES);

    dim3 pgrid(NTILE, BH);
    pack_kv<<<pgrid, PACKNT>>>(K, Kp, V);

    dim3 grid(SEQ / BQ, BH);
    fa5_mma_kernel<<<grid, NT, SMEM_BYTES>>>(Q, Qp, O);
}

// round 9
// speedup vs baseline: 1.4257x; 1.0504x over previous
#include <cuda_runtime.h>
#include <cuda_bf16.h>
#include <cuda_fp16.h>
#include <cstdint>

#define BH    32
#define SEQ   2048
#define D     64
#define BQ    128
#define BK    64
#define NTILE (SEQ / BK)      // 32
#define NW    8
#define NT    256
#define PACKNT 256
#define NSTAGE 4

#define QSCALE 0.18033688011112042f   // 0.125 * log2(e)

// one packed tile image: K fragments (8c x 8j x 32lane x 16B) + V fragments (4c2 x 8jd x 32lane x 8B)
#define KFRAG_B 32768
#define VFRAG_B 8192
#define FRAG_B  (KFRAG_B + VFRAG_B)   // 40960

__device__ __align__(128) unsigned char gF[BH * NTILE * FRAG_B];

// smem: NSTAGE stages of FRAG_B + mbarriers full[4] / empty[4]
#define SM_MBAR  (NSTAGE * FRAG_B)    // 163840
#define SMEM_BYTES (SM_MBAR + 64)

// prepass smem: ks[64][132] + vs[64][68] floats
#define KS_P 132
#define VS_P 68
#define PACK_SMEM ((64 * KS_P + 64 * VS_P) * 4)   // 51200

__device__ __forceinline__ void split2(float x, float y, unsigned &hi, unsigned &lo) {
    __nv_bfloat162 h = __floats2bfloat162_rn(x, y);
    hi = *reinterpret_cast<unsigned*>(&h);
    float rx = x - __bfloat162float(h.x);
    float ry = y - __bfloat162float(h.y);
    __nv_bfloat162 l2 = __floats2bfloat162_rn(rx, ry);
    lo = *reinterpret_cast<unsigned*>(&l2);
}

#define MMAB(c, a, b0, b1)                                                     \
    asm volatile(                                                              \
        "mma.sync.aligned.m16n8k16.row.col.f32.bf16.bf16.f32 "                 \
        "{%0,%1,%2,%3},{%4,%5,%6,%7},{%8,%9},{%0,%1,%2,%3};"                   \
        : "+f"(c[0]), "+f"(c[1]), "+f"(c[2]), "+f"(c[3])                       \
        : "r"(a[0]), "r"(a[1]), "r"(a[2]), "r"(a[3]), "r"(b0), "r"(b1))

#define MMAH(c, a, b0, b1)                                                     \
    asm volatile(                                                              \
        "mma.sync.aligned.m16n8k16.row.col.f32.f16.f16.f32 "                   \
        "{%0,%1,%2,%3},{%4,%5,%6,%7},{%8,%9},{%0,%1,%2,%3};"                   \
        : "+f"(c[0]), "+f"(c[1]), "+f"(c[2]), "+f"(c[3])                       \
        : "r"(a[0]), "r"(a[1]), "r"(a[2]), "r"(a[3]), "r"(b0), "r"(b1))

// ============== pre-pass: pack K|Kp and V^T into fragment-linear order ==============
__global__ __launch_bounds__(PACKNT)
void pack_kv(const float* __restrict__ K, const float* __restrict__ Kp,
             const float* __restrict__ V)
{
    extern __shared__ float psm[];
    float* ks = psm;                   // [64][KS_P], concat features 0..127
    float* vs = psm + 64 * KS_P;       // [64][VS_P]

    const int kt = blockIdx.x, bh = blockIdx.y, tid = threadIdx.x;
    const long plane = (long)bh * SEQ * D;
    const float* Kt  = K  + plane + (long)kt * BK * D;
    const float* Kpt = Kp + plane + (long)kt * BK * D;
    const float* Vt  = V  + plane + (long)kt * BK * D;
    unsigned char* tF = gF + (size_t)(bh * NTILE + kt) * FRAG_B;

    // coalesced stage into smem
    for (int i = tid; i < BK * D; i += PACKNT) {
        int r = i >> 6, d = i & 63;
        ks[r * KS_P + d]      = Kt [r * D + d];
        ks[r * KS_P + 64 + d] = Kpt[r * D + d];
        vs[r * VS_P + d]      = Vt [r * D + d];
    }
    __syncthreads();

    // K fragments: i = (c*8 + j)*32 + lane, 16B each {bh0,bh1,bl0,bl1}
    for (int i = tid; i < 2048; i += PACKNT) {
        int lane = i & 31, j = (i >> 5) & 7, c = i >> 8;
        int g = lane >> 2, t = lane & 3;
        int n = 8 * j + g;
        int d0 = 16 * c + 2 * t;
        float a0 = ks[n * KS_P + d0],     a1 = ks[n * KS_P + d0 + 1];
        float b0 = ks[n * KS_P + d0 + 8], b1 = ks[n * KS_P + d0 + 9];
        unsigned h0, l0, h1, l1;
        split2(a0, a1, h0, l0);
        split2(b0, b1, h1, l1);
        uint4 frag = make_uint4(h0, h1, l0, l1);
        *(uint4*)(tF + (size_t)i * 16) = frag;
    }

    // V fragments: i = (c2*8 + jd)*32 + lane, 8B each {v0,v1} fp16
    for (int i = tid; i < 1024; i += PACKNT) {
        int lane = i & 31, jd = (i >> 5) & 7, c2 = i >> 8;
        int g = lane >> 2, t = lane & 3;
        int d = 8 * jd + g;
        int k0 = 16 * c2 + 2 * t;
        __half2 v0 = __floats2half2_rn(vs[k0 * VS_P + d],       vs[(k0 + 1) * VS_P + d]);
        __half2 v1 = __floats2half2_rn(vs[(k0 + 8) * VS_P + d], vs[(k0 + 9) * VS_P + d]);
        uint2 frag = make_uint2(*reinterpret_cast<unsigned*>(&v0),
                                *reinterpret_cast<unsigned*>(&v1));
        *(uint2*)(tF + KFRAG_B + (size_t)i * 8) = frag;
    }
}

// =============================== main kernel ===============================
__device__ __forceinline__ uint32_t s2u32(const void* p) {
    uint32_t a;
    asm("{ .reg .u64 t; cvta.to.shared.u64 t, %1; cvt.u32.u64 %0, t; }" : "=r"(a) : "l"(p));
    return a;
}

__device__ __forceinline__ void bulk_g2s(uint32_t dst, const void* src,
                                         unsigned bytes, uint32_t mbar) {
    asm volatile(
        "cp.async.bulk.shared::cluster.global.mbarrier::complete_tx::bytes "
        "[%0], [%1], %2, [%3];"
        :: "r"(dst), "l"(src), "r"(bytes), "r"(mbar) : "memory");
}

__device__ __forceinline__ void mbar_wait(uint32_t mbar, unsigned ph) {
    unsigned done = 0;
    while (!done) {
        asm volatile(
            "{ .reg .pred p; "
            "mbarrier.try_wait.parity.acquire.cta.shared::cta.b64 p, [%1], %2, 0x989680; "
            "selp.b32 %0, 1, 0, p; }"
            : "=r"(done) : "r"(mbar), "r"(ph) : "memory");
    }
}

__global__ __launch_bounds__(NT, 1)
void fa6_mma_kernel(const float* __restrict__ Qg,
                    const float* __restrict__ Qpg,
                    float* __restrict__ Og)
{
    extern __shared__ unsigned char sm[];
    const uint32_t smb = s2u32(sm);

    const int bh    = blockIdx.y;
    const int qtile = blockIdx.x;
    const int tid   = threadIdx.x;
    const int w     = tid >> 5;
    const int lane  = tid & 31;
    const int g     = lane >> 2;
    const int t     = lane & 3;

    const long plane = (long)bh * SEQ * D;

    // full[s]: count 1 (tx-based); empty[s]: count NW
    if (tid == 0) {
        #pragma unroll
        for (int s = 0; s < NSTAGE; s++) {
            asm volatile("mbarrier.init.shared.b64 [%0], 1;"
                         :: "r"(smb + SM_MBAR + s * 8) : "memory");
            asm volatile("mbarrier.init.shared.b64 [%0], %1;"
                         :: "r"(smb + SM_MBAR + 32 + s * 8), "r"(NW) : "memory");
        }
    }
    __syncthreads();

    // ---- Q fragments in registers (scale folded) ----
    unsigned qhi[8][4], qlo[8][4];
    {
        const float* Qpl  = Qg  + plane;
        const float* Qppl = Qpg + plane;
        const int r0 = qtile * BQ + w * 16 + g;
        #pragma unroll
        for (int c = 0; c < 8; c++) {
            const float* S = (c < 4) ? Qpl : Qppl;
            const int cb = (c & 3) * 16;
            float2 x0 = *(const float2*)&S[(long)r0 * D + cb + 2 * t];
            float2 x1 = *(const float2*)&S[(long)(r0 + 8) * D + cb + 2 * t];
            float2 x2 = *(const float2*)&S[(long)r0 * D + cb + 8 + 2 * t];
            float2 x3 = *(const float2*)&S[(long)(r0 + 8) * D + cb + 8 + 2 * t];
            split2(x0.x * QSCALE, x0.y * QSCALE, qhi[c][0], qlo[c][0]);
            split2(x1.x * QSCALE, x1.y * QSCALE, qhi[c][1], qlo[c][1]);
            split2(x2.x * QSCALE, x2.y * QSCALE, qhi[c][2], qlo[c][2]);
            split2(x3.x * QSCALE, x3.y * QSCALE, qhi[c][3], qlo[c][3]);
        }
    }

    float ov[8][4];
    #pragma unroll
    for (int j = 0; j < 8; j++) { ov[j][0]=0.f; ov[j][1]=0.f; ov[j][2]=0.f; ov[j][3]=0.f; }
    float m0 = -1e30f, m1 = -1e30f, l0 = 0.f, l1 = 0.f;

    const unsigned char* baseF = gF + (size_t)bh * NTILE * FRAG_B;

    auto issue = [&](int T) {            // load tile T into stage T%NSTAGE (single bulk copy)
        const int s = T % NSTAGE;
        const uint32_t mb = smb + SM_MBAR + s * 8;
        asm volatile("mbarrier.arrive.expect_tx.shared.b64 _, [%0], %1;"
                     :: "r"(mb), "r"((unsigned)FRAG_B) : "memory");
        bulk_g2s(smb + s * FRAG_B, baseF + (size_t)T * FRAG_B, FRAG_B, mb);
    };

    if (tid == 0) { issue(0); issue(1); issue(2); issue(3); }

    for (int kt = 0; kt < NTILE; kt++) {
        const int s = kt % NSTAGE;
        const unsigned rph = (unsigned)((kt / NSTAGE) & 1);

        mbar_wait(smb + SM_MBAR + s * 8, rph);

        const uint4* Kf = (const uint4*)(sm + s * FRAG_B);
        const uint2* Vf = (const uint2*)(sm + s * FRAG_B + KFRAG_B);

        // ---- QK^T: 3-MMA split bf16, fragment-linear LDS.128 ----
        float sc[8][4];
        #pragma unroll
        for (int j = 0; j < 8; j++) { sc[j][0]=0.f; sc[j][1]=0.f; sc[j][2]=0.f; sc[j][3]=0.f; }

        #pragma unroll
        for (int c = 0; c < 8; c++) {
            #pragma unroll
            for (int j = 0; j < 8; j++) {
                uint4 kf = Kf[(c * 8 + j) * 32 + lane];
                MMAB(sc[j], qhi[c], kf.x, kf.y);
                MMAB(sc[j], qhi[c], kf.z, kf.w);
                MMAB(sc[j], qlo[c], kf.x, kf.y);
            }
        }

        // ---- online softmax (log2 domain) ----
        float mx0 = -1e30f, mx1 = -1e30f;
        #pragma unroll
        for (int j = 0; j < 8; j++) {
            mx0 = fmaxf(mx0, fmaxf(sc[j][0], sc[j][1]));
            mx1 = fmaxf(mx1, fmaxf(sc[j][2], sc[j][3]));
        }
        mx0 = fmaxf(mx0, __shfl_xor_sync(0xffffffffu, mx0, 1));
        mx0 = fmaxf(mx0, __shfl_xor_sync(0xffffffffu, mx0, 2));
        mx1 = fmaxf(mx1, __shfl_xor_sync(0xffffffffu, mx1, 1));
        mx1 = fmaxf(mx1, __shfl_xor_sync(0xffffffffu, mx1, 2));

        float mn0 = fmaxf(m0, mx0), mn1 = fmaxf(m1, mx1);
        float f0 = exp2f(m0 - mn0), f1 = exp2f(m1 - mn1);
        m0 = mn0; m1 = mn1;

        float s0 = 0.f, s1 = 0.f;
        #pragma unroll
        for (int j = 0; j < 8; j++) {
            sc[j][0] = exp2f(sc[j][0] - m0); s0 += sc[j][0];
            sc[j][1] = exp2f(sc[j][1] - m0); s0 += sc[j][1];
            sc[j][2] = exp2f(sc[j][2] - m1); s1 += sc[j][2];
            sc[j][3] = exp2f(sc[j][3] - m1); s1 += sc[j][3];
        }
        s0 += __shfl_xor_sync(0xffffffffu, s0, 1);
        s0 += __shfl_xor_sync(0xffffffffu, s0, 2);
        s1 += __shfl_xor_sync(0xffffffffu, s1, 1);
        s1 += __shfl_xor_sync(0xffffffffu, s1, 2);
        l0 = l0 * f0 + s0;
        l1 = l1 * f1 + s1;

        #pragma unroll
        for (int j = 0; j < 8; j++) {
            ov[j][0] *= f0; ov[j][1] *= f0; ov[j][2] *= f1; ov[j][3] *= f1;
        }

        // ---- PV: single fp16 MMA, fragment-linear LDS.64 ----
        #pragma unroll
        for (int c2 = 0; c2 < 4; c2++) {
            unsigned pa[4];
            __half2 h0 = __floats2half2_rn(sc[2*c2][0],   sc[2*c2][1]);
            __half2 h1 = __floats2half2_rn(sc[2*c2][2],   sc[2*c2][3]);
            __half2 h2 = __floats2half2_rn(sc[2*c2+1][0], sc[2*c2+1][1]);
            __half2 h3 = __floats2half2_rn(sc[2*c2+1][2], sc[2*c2+1][3]);
            pa[0] = *reinterpret_cast<unsigned*>(&h0);
            pa[1] = *reinterpret_cast<unsigned*>(&h1);
            pa[2] = *reinterpret_cast<unsigned*>(&h2);
            pa[3] = *reinterpret_cast<unsigned*>(&h3);
            #pragma unroll
            for (int jd = 0; jd < 8; jd++) {
                uint2 vf = Vf[(c2 * 8 + jd) * 32 + lane];
                MMAH(ov[jd], pa, vf.x, vf.y);
            }
        }

        // consumer: done with stage s
        if (lane == 0) {
            asm volatile("mbarrier.arrive.shared.b64 _, [%0];"
                         :: "r"(smb + SM_MBAR + 32 + s * 8) : "memory");
        }

        // rotating producer: warp (kt&7) refills stage s with tile kt+NSTAGE
        if (w == (kt & 7) && kt + NSTAGE < NTILE) {
            if (lane == 0) {
                mbar_wait(smb + SM_MBAR + 32 + s * 8, rph);
                issue(kt + NSTAGE);
            }
        }
    }

    // ---- epilogue ----
    {
        float inv0 = 1.0f / l0, inv1 = 1.0f / l1;
        const int r0 = qtile * BQ + w * 16 + g;
        float* O = Og + plane;
        #pragma unroll
        for (int jd = 0; jd < 8; jd++) {
            int col = 8 * jd + 2 * t;
            float2 a = make_float2(ov[jd][0] * inv0, ov[jd][1] * inv0);
            float2 b = make_float2(ov[jd][2] * inv1, ov[jd][3] * inv1);
            *(float2*)&O[(long)r0 * D + col]       = a;
            *(float2*)&O[(long)(r0 + 8) * D + col] = b;
        }
    }
}

extern "C" void kernel_launch(void* const* d_in, const int* in_sizes, int n_in,
                              void* d_out, int out_size)
{
    const float* Q  = (const float*)d_in[0];
    const float* K  = (const float*)d_in[1];
    const float* V  = (const float*)d_in[2];
    const float* Qp = (const float*)d_in[3];
    const float* Kp = (const float*)d_in[4];
    float* O = (float*)d_out;

    cudaFuncSetAttribute(fa6_mma_kernel,
                         cudaFuncAttributeMaxDynamicSharedMemorySize, SMEM_BYTES);
    cudaFuncSetAttribute(pack_kv,
                         cudaFuncAttributeMaxDynamicSharedMemorySize, PACK_SMEM);

    dim3 pgrid(NTILE, BH);
    pack_kv<<<pgrid, PACKNT, PACK_SMEM>>>(K, Kp, V);

    dim3 grid(SEQ / BQ, BH);
    fa6_mma_kernel<<<grid, NT, SMEM_BYTES>>>(Q, Qp, O);
}

// round 10
// speedup vs baseline: 1.4447x; 1.0133x over previous
#include <cuda_runtime.h>
#include <cuda_bf16.h>
#include <cuda_fp16.h>
#include <cstdint>

#define BH    32
#define SEQ   2048
#define D     64
#define BQ    128
#define BK    64
#define NTILE (SEQ / BK)      // 32
#define NW    8
#define NT    256
#define PACKNT 256
#define NSTAGE 4

#define QSCALE 0.18033688011112042f   // 0.125 * log2(e)

// one packed tile image: K fragments (8c x 8j x 32lane x 16B) + V fragments (4c2 x 8jd x 32lane x 8B)
#define KFRAG_B 32768
#define VFRAG_B 8192
#define FRAG_B  (KFRAG_B + VFRAG_B)   // 40960

__device__ __align__(128) unsigned char gF[BH * NTILE * FRAG_B];

// smem: NSTAGE stages of FRAG_B + mbarriers full[4] / empty[4]
#define SM_MBAR  (NSTAGE * FRAG_B)    // 163840
#define SMEM_BYTES (SM_MBAR + 64)

// prepass smem: ks[64][132] + vs[64][68] floats
#define KS_P 132
#define VS_P 68
#define PACK_SMEM ((64 * KS_P + 64 * VS_P) * 4)   // 51200

__device__ __forceinline__ void split2(float x, float y, unsigned &hi, unsigned &lo) {
    __nv_bfloat162 h = __floats2bfloat162_rn(x, y);
    hi = *reinterpret_cast<unsigned*>(&h);
    float rx = x - __bfloat162float(h.x);
    float ry = y - __bfloat162float(h.y);
    __nv_bfloat162 l2 = __floats2bfloat162_rn(rx, ry);
    lo = *reinterpret_cast<unsigned*>(&l2);
}

#define MMAB(c, a, b0, b1)                                                     \
    asm volatile(                                                              \
        "mma.sync.aligned.m16n8k16.row.col.f32.bf16.bf16.f32 "                 \
        "{%0,%1,%2,%3},{%4,%5,%6,%7},{%8,%9},{%0,%1,%2,%3};"                   \
        : "+f"(c[0]), "+f"(c[1]), "+f"(c[2]), "+f"(c[3])                       \
        : "r"(a[0]), "r"(a[1]), "r"(a[2]), "r"(a[3]), "r"(b0), "r"(b1))

#define MMAH(c, a, b0, b1)                                                     \
    asm volatile(                                                              \
        "mma.sync.aligned.m16n8k16.row.col.f32.f16.f16.f32 "                   \
        "{%0,%1,%2,%3},{%4,%5,%6,%7},{%8,%9},{%0,%1,%2,%3};"                   \
        : "+f"(c[0]), "+f"(c[1]), "+f"(c[2]), "+f"(c[3])                       \
        : "r"(a[0]), "r"(a[1]), "r"(a[2]), "r"(a[3]), "r"(b0), "r"(b1))

// ============== pre-pass: pack K|Kp and V^T into fragment-linear order ==============
__global__ __launch_bounds__(PACKNT)
void pack_kv(const float* __restrict__ K, const float* __restrict__ Kp,
             const float* __restrict__ V)
{
    extern __shared__ float psm[];
    float* ks = psm;                   // [64][KS_P], concat features 0..127
    float* vs = psm + 64 * KS_P;       // [64][VS_P]

    const int kt = blockIdx.x, bh = blockIdx.y, tid = threadIdx.x;
    const long plane = (long)bh * SEQ * D;
    const float* Kt  = K  + plane + (long)kt * BK * D;
    const float* Kpt = Kp + plane + (long)kt * BK * D;
    const float* Vt  = V  + plane + (long)kt * BK * D;
    unsigned char* tF = gF + (size_t)(bh * NTILE + kt) * FRAG_B;

    // coalesced stage into smem
    for (int i = tid; i < BK * D; i += PACKNT) {
        int r = i >> 6, d = i & 63;
        ks[r * KS_P + d]      = Kt [r * D + d];
        ks[r * KS_P + 64 + d] = Kpt[r * D + d];
        vs[r * VS_P + d]      = Vt [r * D + d];
    }
    __syncthreads();

    // K fragments: i = (c*8 + j)*32 + lane, 16B each {bh0,bh1,bl0,bl1}
    for (int i = tid; i < 2048; i += PACKNT) {
        int lane = i & 31, j = (i >> 5) & 7, c = i >> 8;
        int g = lane >> 2, t = lane & 3;
        int n = 8 * j + g;
        int d0 = 16 * c + 2 * t;
        float a0 = ks[n * KS_P + d0],     a1 = ks[n * KS_P + d0 + 1];
        float b0 = ks[n * KS_P + d0 + 8], b1 = ks[n * KS_P + d0 + 9];
        unsigned h0, l0, h1, l1;
        split2(a0, a1, h0, l0);
        split2(b0, b1, h1, l1);
        uint4 frag = make_uint4(h0, h1, l0, l1);
        *(uint4*)(tF + (size_t)i * 16) = frag;
    }

    // V fragments: i = (c2*8 + jd)*32 + lane, 8B each {v0,v1} fp16
    for (int i = tid; i < 1024; i += PACKNT) {
        int lane = i & 31, jd = (i >> 5) & 7, c2 = i >> 8;
        int g = lane >> 2, t = lane & 3;
        int d = 8 * jd + g;
        int k0 = 16 * c2 + 2 * t;
        __half2 v0 = __floats2half2_rn(vs[k0 * VS_P + d],       vs[(k0 + 1) * VS_P + d]);
        __half2 v1 = __floats2half2_rn(vs[(k0 + 8) * VS_P + d], vs[(k0 + 9) * VS_P + d]);
        uint2 frag = make_uint2(*reinterpret_cast<unsigned*>(&v0),
                                *reinterpret_cast<unsigned*>(&v1));
        *(uint2*)(tF + KFRAG_B + (size_t)i * 8) = frag;
    }
}

// =============================== main kernel ===============================
__device__ __forceinline__ uint32_t s2u32(const void* p) {
    uint32_t a;
    asm("{ .reg .u64 t; cvta.to.shared.u64 t, %1; cvt.u32.u64 %0, t; }" : "=r"(a) : "l"(p));
    return a;
}

__device__ __forceinline__ void bulk_g2s(uint32_t dst, const void* src,
                                         unsigned bytes, uint32_t mbar) {
    asm volatile(
        "cp.async.bulk.shared::cluster.global.mbarrier::complete_tx::bytes "
        "[%0], [%1], %2, [%3];"
        :: "r"(dst), "l"(src), "r"(bytes), "r"(mbar) : "memory");
}

__device__ __forceinline__ void mbar_wait(uint32_t mbar, unsigned ph) {
    unsigned done = 0;
    while (!done) {
        asm volatile(
            "{ .reg .pred p; "
            "mbarrier.try_wait.parity.acquire.cta.shared::cta.b64 p, [%1], %2, 0x989680; "
            "selp.b32 %0, 1, 0, p; }"
            : "=r"(done) : "r"(mbar), "r"(ph) : "memory");
    }
}

__global__ __launch_bounds__(NT, 1)
void fa7_mma_kernel(const float* __restrict__ Qg,
                    const float* __restrict__ Qpg,
                    float* __restrict__ Og)
{
    extern __shared__ unsigned char sm[];
    const uint32_t smb = s2u32(sm);

    const int bh    = blockIdx.y;
    const int qtile = blockIdx.x;
    const int tid   = threadIdx.x;
    const int w     = tid >> 5;
    const int lane  = tid & 31;
    const int g     = lane >> 2;
    const int t     = lane & 3;

    const long plane = (long)bh * SEQ * D;

    // full[s]: count 1 (tx-based); empty[s]: count NW
    if (tid == 0) {
        #pragma unroll
        for (int s = 0; s < NSTAGE; s++) {
            asm volatile("mbarrier.init.shared.b64 [%0], 1;"
                         :: "r"(smb + SM_MBAR + s * 8) : "memory");
            asm volatile("mbarrier.init.shared.b64 [%0], %1;"
                         :: "r"(smb + SM_MBAR + 32 + s * 8), "r"(NW) : "memory");
        }
    }
    __syncthreads();

    // ---- Q fragments in registers (scale folded) ----
    unsigned qhi[8][4], qlo[8][4];
    {
        const float* Qpl  = Qg  + plane;
        const float* Qppl = Qpg + plane;
        const int r0 = qtile * BQ + w * 16 + g;
        #pragma unroll
        for (int c = 0; c < 8; c++) {
            const float* S = (c < 4) ? Qpl : Qppl;
            const int cb = (c & 3) * 16;
            float2 x0 = *(const float2*)&S[(long)r0 * D + cb + 2 * t];
            float2 x1 = *(const float2*)&S[(long)(r0 + 8) * D + cb + 2 * t];
            float2 x2 = *(const float2*)&S[(long)r0 * D + cb + 8 + 2 * t];
            float2 x3 = *(const float2*)&S[(long)(r0 + 8) * D + cb + 8 + 2 * t];
            split2(x0.x * QSCALE, x0.y * QSCALE, qhi[c][0], qlo[c][0]);
            split2(x1.x * QSCALE, x1.y * QSCALE, qhi[c][1], qlo[c][1]);
            split2(x2.x * QSCALE, x2.y * QSCALE, qhi[c][2], qlo[c][2]);
            split2(x3.x * QSCALE, x3.y * QSCALE, qhi[c][3], qlo[c][3]);
        }
    }

    float ov[8][4];
    #pragma unroll
    for (int j = 0; j < 8; j++) { ov[j][0]=0.f; ov[j][1]=0.f; ov[j][2]=0.f; ov[j][3]=0.f; }
    float m0 = -1e30f, m1 = -1e30f, l0 = 0.f, l1 = 0.f;

    const unsigned char* baseF = gF + (size_t)bh * NTILE * FRAG_B;

    auto issue = [&](int T) {            // load tile T into stage T%NSTAGE (single bulk copy)
        const int s = T % NSTAGE;
        const uint32_t mb = smb + SM_MBAR + s * 8;
        asm volatile("mbarrier.arrive.expect_tx.shared.b64 _, [%0], %1;"
                     :: "r"(mb), "r"((unsigned)FRAG_B) : "memory");
        bulk_g2s(smb + s * FRAG_B, baseF + (size_t)T * FRAG_B, FRAG_B, mb);
    };

    if (tid == 0) { issue(0); issue(1); issue(2); issue(3); }

    // QK^T MMAs for tile kt into sc (assumes stage kt%NSTAGE already full-waited)
    auto qk = [&](int kt, float (&sc)[8][4]) {
        const uint4* Kf = (const uint4*)(sm + (kt % NSTAGE) * FRAG_B);
        #pragma unroll
        for (int j = 0; j < 8; j++) { sc[j][0]=0.f; sc[j][1]=0.f; sc[j][2]=0.f; sc[j][3]=0.f; }
        #pragma unroll
        for (int c = 0; c < 8; c++) {
            #pragma unroll
            for (int j = 0; j < 8; j++) {
                uint4 kf = Kf[(c * 8 + j) * 32 + lane];
                MMAB(sc[j], qhi[c], kf.x, kf.y);
                MMAB(sc[j], qhi[c], kf.z, kf.w);
                MMAB(sc[j], qlo[c], kf.x, kf.y);
            }
        }
    };

    // softmax + PV for tile kt on sc, then release stage; rotating producer refill
    auto smax_pv = [&](int kt, float (&sc)[8][4]) {
        const int s = kt % NSTAGE;
        const unsigned rph = (unsigned)((kt / NSTAGE) & 1);

        float mx0 = -1e30f, mx1 = -1e30f;
        #pragma unroll
        for (int j = 0; j < 8; j++) {
            mx0 = fmaxf(mx0, fmaxf(sc[j][0], sc[j][1]));
            mx1 = fmaxf(mx1, fmaxf(sc[j][2], sc[j][3]));
        }
        mx0 = fmaxf(mx0, __shfl_xor_sync(0xffffffffu, mx0, 1));
        mx0 = fmaxf(mx0, __shfl_xor_sync(0xffffffffu, mx0, 2));
        mx1 = fmaxf(mx1, __shfl_xor_sync(0xffffffffu, mx1, 1));
        mx1 = fmaxf(mx1, __shfl_xor_sync(0xffffffffu, mx1, 2));

        float mn0 = fmaxf(m0, mx0), mn1 = fmaxf(m1, mx1);
        float f0 = exp2f(m0 - mn0), f1 = exp2f(m1 - mn1);
        m0 = mn0; m1 = mn1;

        float s0 = 0.f, s1 = 0.f;
        #pragma unroll
        for (int j = 0; j < 8; j++) {
            sc[j][0] = exp2f(sc[j][0] - m0); s0 += sc[j][0];
            sc[j][1] = exp2f(sc[j][1] - m0); s0 += sc[j][1];
            sc[j][2] = exp2f(sc[j][2] - m1); s1 += sc[j][2];
            sc[j][3] = exp2f(sc[j][3] - m1); s1 += sc[j][3];
        }
        s0 += __shfl_xor_sync(0xffffffffu, s0, 1);
        s0 += __shfl_xor_sync(0xffffffffu, s0, 2);
        s1 += __shfl_xor_sync(0xffffffffu, s1, 1);
        s1 += __shfl_xor_sync(0xffffffffu, s1, 2);
        l0 = l0 * f0 + s0;
        l1 = l1 * f1 + s1;

        #pragma unroll
        for (int j = 0; j < 8; j++) {
            ov[j][0] *= f0; ov[j][1] *= f0; ov[j][2] *= f1; ov[j][3] *= f1;
        }

        const uint2* Vf = (const uint2*)(sm + s * FRAG_B + KFRAG_B);
        #pragma unroll
        for (int c2 = 0; c2 < 4; c2++) {
            unsigned pa[4];
            __half2 h0 = __floats2half2_rn(sc[2*c2][0],   sc[2*c2][1]);
            __half2 h1 = __floats2half2_rn(sc[2*c2][2],   sc[2*c2][3]);
            __half2 h2 = __floats2half2_rn(sc[2*c2+1][0], sc[2*c2+1][1]);
            __half2 h3 = __floats2half2_rn(sc[2*c2+1][2], sc[2*c2+1][3]);
            pa[0] = *reinterpret_cast<unsigned*>(&h0);
            pa[1] = *reinterpret_cast<unsigned*>(&h1);
            pa[2] = *reinterpret_cast<unsigned*>(&h2);
            pa[3] = *reinterpret_cast<unsigned*>(&h3);
            #pragma unroll
            for (int jd = 0; jd < 8; jd++) {
                uint2 vf = Vf[(c2 * 8 + jd) * 32 + lane];
                MMAH(ov[jd], pa, vf.x, vf.y);
            }
        }

        // release stage s
        if (lane == 0) {
            asm volatile("mbarrier.arrive.shared.b64 _, [%0];"
                         :: "r"(smb + SM_MBAR + 32 + s * 8) : "memory");
        }
        // rotating producer: refill stage s with tile kt+NSTAGE
        if (w == (kt & 7) && kt + NSTAGE < NTILE) {
            if (lane == 0) {
                mbar_wait(smb + SM_MBAR + 32 + s * 8, rph);
                issue(kt + NSTAGE);
            }
        }
    };

    float scA[8][4], scB[8][4];

    // prologue: QK(0) queued before the loop
    mbar_wait(smb + SM_MBAR + 0, 0);
    qk(0, scA);

    for (int kt = 0; kt < NTILE; kt += 2) {
        // QK(kt+1) fills tensor pipe during softmax(kt)
        mbar_wait(smb + SM_MBAR + ((kt + 1) % NSTAGE) * 8,
                  (unsigned)(((kt + 1) / NSTAGE) & 1));
        qk(kt + 1, scB);
        smax_pv(kt, scA);

        // QK(kt+2) fills tensor pipe during softmax(kt+1)
        if (kt + 2 < NTILE) {
            mbar_wait(smb + SM_MBAR + ((kt + 2) % NSTAGE) * 8,
                      (unsigned)(((kt + 2) / NSTAGE) & 1));
            qk(kt + 2, scA);
        }
        smax_pv(kt + 1, scB);
    }

    // ---- epilogue ----
    {
        float inv0 = 1.0f / l0, inv1 = 1.0f / l1;
        const int r0 = qtile * BQ + w * 16 + g;
        float* O = Og + plane;
        #pragma unroll
        for (int jd = 0; jd < 8; jd++) {
            int col = 8 * jd + 2 * t;
            float2 a = make_float2(ov[jd][0] * inv0, ov[jd][1] * inv0);
            float2 b = make_float2(ov[jd][2] * inv1, ov[jd][3] * inv1);
            *(float2*)&O[(long)r0 * D + col]       = a;
            *(float2*)&O[(long)(r0 + 8) * D + col] = b;
        }
    }
}

extern "C" void kernel_launch(void* const* d_in, const int* in_sizes, int n_in,
                              void* d_out, int out_size)
{
    const float* Q  = (const float*)d_in[0];
    const float* K  = (const float*)d_in[1];
    const float* V  = (const float*)d_in[2];
    const float* Qp = (const float*)d_in[3];
    const float* Kp = (const float*)d_in[4];
    float* O = (float*)d_out;

    cudaFuncSetAttribute(fa7_mma_kernel,
                         cudaFuncAttributeMaxDynamicSharedMemorySize, SMEM_BYTES);
    cudaFuncSetAttribute(pack_kv,
                         cudaFuncAttributeMaxDynamicSharedMemorySize, PACK_SMEM);

    dim3 pgrid(NTILE, BH);
    pack_kv<<<pgrid, PACKNT, PACK_SMEM>>>(K, Kp, V);

    dim3 grid(SEQ / BQ, BH);
    fa7_mma_kernel<<<grid, NT, SMEM_BYTES>>>(Q, Qp, O);
}